// round 1
// baseline (speedup 1.0000x reference)
#include <cuda_runtime.h>
#include <cuda_bf16.h>
#include <math.h>

// ---------------------------------------------------------------------------
// Problem: out[32,1024] = concat_c( weighted_spatial_mean(feat_l) ) @ conv_w.T
// where the weighted mean exactly reproduces bilinear-upsample(56x56)+mean.
// Levels: feat0 [32,256,56,56], feat1 [32,512,28,28], feat2 [32,1024,14,14],
//         feat3 [32,2048,7,7];  conv_w [1024, 3840].
// ---------------------------------------------------------------------------

#define OUT_HW 56
#define BATCH  32
#define CTOT   3840
#define EMB    1024

// Scratch (allocation-free rule: __device__ globals)
__device__ float g_v[BATCH * CTOT];     // pooled vector [32,3840]
__device__ float g_W[4 * 64];           // per-level source-pixel weights (padded rows)

// ---------------------------------------------------------------------------
// Kernel 0: compute per-source-row total bilinear weight W[s] for each level.
// Replicates jax.image.resize('bilinear') triangle kernel + row renorm.
// ---------------------------------------------------------------------------
__global__ void weights_kernel() {
    const int ins[4] = {56, 28, 14, 7};
    int s = threadIdx.x;  // 64 threads
    #pragma unroll
    for (int lvl = 0; lvl < 4; lvl++) {
        int in = ins[lvl];
        if (s < in) {
            float ratio = (float)in / (float)OUT_HW;  // exact (1, .5, .25, .125)
            float acc = 0.f;
            for (int t = 0; t < OUT_HW; t++) {
                float sf = ((float)t + 0.5f) * ratio - 0.5f;
                float fi = floorf(sf);
                int   i0 = (int)fi;
                float fr = sf - fi;
                float w0 = 1.f - fr;
                float w1 = fr;
                float rs = 0.f;
                if (i0 >= 0 && i0 < in)     rs += w0;
                if (i0 + 1 >= 0 && i0 + 1 < in) rs += w1;
                float inv = 1.f / rs;
                if (i0 == s)     acc += w0 * inv;
                if (i0 + 1 == s) acc += w1 * inv;
            }
            g_W[lvl * 64 + s] = acc;
        }
    }
}

// ---------------------------------------------------------------------------
// Kernel 1 (x4): weighted spatial mean per (b, c). One block per plane.
// Templated on IN so index div/mod compiles to mul-shift; float4 loads when
// the plane size is a multiple of 4.
// ---------------------------------------------------------------------------
template <int IN>
__global__ void pool_kernel(const float* __restrict__ f, int C, int lvl, int c_off) {
    __shared__ float Ws[IN];
    __shared__ float red[8];

    int bc = blockIdx.x;
    int b  = bc / C;
    int c  = bc - b * C;
    const float* plane = f + (size_t)bc * (IN * IN);

    for (int s = threadIdx.x; s < IN; s += blockDim.x)
        Ws[s] = g_W[lvl * 64 + s];
    __syncthreads();

    float sum = 0.f;
    if ((IN * IN) % 4 == 0) {
        const float4* p4 = (const float4*)plane;
        const int N4 = (IN * IN) / 4;
        for (int i = threadIdx.x; i < N4; i += blockDim.x) {
            float4 v = p4[i];
            int base = i * 4;
            int i0 = base, i1 = base + 1, i2 = base + 2, i3 = base + 3;
            sum += v.x * Ws[i0 / IN] * Ws[i0 % IN];
            sum += v.y * Ws[i1 / IN] * Ws[i1 % IN];
            sum += v.z * Ws[i2 / IN] * Ws[i2 % IN];
            sum += v.w * Ws[i3 / IN] * Ws[i3 % IN];
        }
    } else {
        for (int i = threadIdx.x; i < IN * IN; i += blockDim.x) {
            sum += plane[i] * Ws[i / IN] * Ws[i % IN];
        }
    }

    // block reduce
    int lane = threadIdx.x & 31;
    int wid  = threadIdx.x >> 5;
    #pragma unroll
    for (int o = 16; o > 0; o >>= 1)
        sum += __shfl_down_sync(0xFFFFFFFFu, sum, o);
    if (lane == 0) red[wid] = sum;
    __syncthreads();
    if (threadIdx.x == 0) {
        float s = 0.f;
        int nw = (blockDim.x + 31) >> 5;
        for (int w = 0; w < nw; w++) s += red[w];
        g_v[b * CTOT + c_off + c] = s * (1.0f / (OUT_HW * OUT_HW));
    }
}

// ---------------------------------------------------------------------------
// Kernel 2: out[32,1024] += v[32,3840] @ W[1024,3840]^T, split-K with atomics.
// Tile: 32 b x 64 e per block; each thread owns a 2b x 4e microtile.
// Grid: (EMB/64 = 16, KSPLIT = 20), K chunk = 192, inner KC = 32.
// ---------------------------------------------------------------------------
#define GEMM_ETILE 64
#define GEMM_KC    32
#define GEMM_KCHUNK 192
#define GEMM_KSPLIT 20

__global__ __launch_bounds__(256)
void gemm_kernel(const float* __restrict__ w, float* __restrict__ out) {
    __shared__ float vs[BATCH][GEMM_KC + 1];        // [b][kk]
    __shared__ float ws[GEMM_ETILE][GEMM_KC + 1];   // [e][kk]

    const int tid   = threadIdx.x;
    const int e0    = blockIdx.x * GEMM_ETILE;
    const int k0    = blockIdx.y * GEMM_KCHUNK;
    const int e_sub = tid & 15;   // 16 groups of 4 e
    const int b_sub = tid >> 4;   // 16 groups of 2 b

    float acc[2][4];
    #pragma unroll
    for (int i = 0; i < 2; i++)
        #pragma unroll
        for (int j = 0; j < 4; j++) acc[i][j] = 0.f;

    for (int kc = 0; kc < GEMM_KCHUNK; kc += GEMM_KC) {
        int kbase = k0 + kc;
        // load v chunk: 32*32 = 1024 floats
        for (int idx = tid; idx < BATCH * GEMM_KC; idx += 256) {
            int b  = idx >> 5;
            int kk = idx & 31;
            vs[b][kk] = g_v[b * CTOT + kbase + kk];
        }
        // load w chunk: 64*32 = 2048 floats
        for (int idx = tid; idx < GEMM_ETILE * GEMM_KC; idx += 256) {
            int e  = idx >> 5;
            int kk = idx & 31;
            ws[e][kk] = w[(size_t)(e0 + e) * CTOT + kbase + kk];
        }
        __syncthreads();

        #pragma unroll
        for (int kk = 0; kk < GEMM_KC; kk++) {
            float a0 = vs[2 * b_sub + 0][kk];
            float a1 = vs[2 * b_sub + 1][kk];
            float w0 = ws[4 * e_sub + 0][kk];
            float w1 = ws[4 * e_sub + 1][kk];
            float w2 = ws[4 * e_sub + 2][kk];
            float w3 = ws[4 * e_sub + 3][kk];
            acc[0][0] += a0 * w0; acc[0][1] += a0 * w1;
            acc[0][2] += a0 * w2; acc[0][3] += a0 * w3;
            acc[1][0] += a1 * w0; acc[1][1] += a1 * w1;
            acc[1][2] += a1 * w2; acc[1][3] += a1 * w3;
        }
        __syncthreads();
    }

    #pragma unroll
    for (int i = 0; i < 2; i++) {
        int b = 2 * b_sub + i;
        #pragma unroll
        for (int j = 0; j < 4; j++) {
            int e = e0 + 4 * e_sub + j;
            atomicAdd(&out[b * EMB + e], acc[i][j]);
        }
    }
}

// ---------------------------------------------------------------------------
extern "C" void kernel_launch(void* const* d_in, const int* in_sizes, int n_in,
                              void* d_out, int out_size) {
    const float* feat0  = (const float*)d_in[0];
    const float* feat1  = (const float*)d_in[1];
    const float* feat2  = (const float*)d_in[2];
    const float* feat3  = (const float*)d_in[3];
    const float* conv_w = (const float*)d_in[4];
    float* out = (float*)d_out;

    weights_kernel<<<1, 64>>>();

    pool_kernel<56><<<BATCH * 256,  256>>>(feat0, 256,  0, 0);
    pool_kernel<28><<<BATCH * 512,  128>>>(feat1, 512,  1, 256);
    pool_kernel<14><<<BATCH * 1024,  64>>>(feat2, 1024, 2, 768);
    pool_kernel< 7><<<BATCH * 2048,  64>>>(feat3, 2048, 3, 1792);

    cudaMemsetAsync(d_out, 0, (size_t)out_size * sizeof(float), 0);

    dim3 grid(EMB / GEMM_ETILE, GEMM_KSPLIT);
    gemm_kernel<<<grid, 256>>>(conv_w, out);
}

// round 2
// speedup vs baseline: 2.2065x; 2.2065x over previous
#include <cuda_runtime.h>
#include <cuda_bf16.h>

// ---------------------------------------------------------------------------
// out[32,1024] = concat_c( spatial_mean(feat_l) ) @ conv_w.T
//
// Key math fact: jax bilinear half-pixel upsample (ratios 1,2,4,8) followed by
// spatial mean gives EXACTLY uniform per-source-pixel weights (edge
// renormalization included) -> pooling is a plain per-plane mean.
// Levels: feat0 [32,256,56,56], feat1 [32,512,28,28], feat2 [32,1024,14,14],
//         feat3 [32,2048,7,7];  conv_w [1024, 3840].
// ---------------------------------------------------------------------------

#define BATCH 32
#define CTOT  3840
#define EMB   1024

__device__ float g_v[BATCH * CTOT];   // pooled vector [32,3840]

// ---------------------------------------------------------------------------
// Pooling: warp per plane, PPW planes per warp. NF4 = float4 per plane.
// Plane sizes are multiples of 16B for levels 0..2.
// ---------------------------------------------------------------------------
template <int NF4, int PPW, int LOGC>
__global__ __launch_bounds__(256)
void pool_warp_kernel(const float* __restrict__ f, int c_off, float scale) {
    const int lane = threadIdx.x & 31;
    const int gwarp = (blockIdx.x * blockDim.x + threadIdx.x) >> 5;

    #pragma unroll
    for (int it = 0; it < PPW; it++) {
        const int plane = gwarp * PPW + it;
        const float4* __restrict__ p = (const float4*)f + (size_t)plane * NF4;

        float s = 0.f;
        #pragma unroll 8
        for (int i = lane; i < NF4; i += 32) {
            float4 v = p[i];
            s += (v.x + v.y) + (v.z + v.w);
        }
        #pragma unroll
        for (int o = 16; o > 0; o >>= 1)
            s += __shfl_down_sync(0xFFFFFFFFu, s, o);

        if (lane == 0) {
            const int b = plane >> LOGC;
            const int c = plane & ((1 << LOGC) - 1);
            g_v[b * CTOT + c_off + c] = s * scale;
        }
    }
}

// ---------------------------------------------------------------------------
// 7x7 level: planes are 196 B (not 16B aligned), so a warp handles groups of
// 4 planes = 49 float4 (784 B, aligned). Per element, select one of 4
// per-plane accumulators with predicated adds (no dynamic indexing).
// ---------------------------------------------------------------------------
#define P7_GPW 8   // groups (of 4 planes) per warp

__global__ __launch_bounds__(256)
void pool7_kernel(const float* __restrict__ f, int c_off, float scale) {
    const int lane  = threadIdx.x & 31;
    const int gwarp = (blockIdx.x * blockDim.x + threadIdx.x) >> 5;

    for (int it = 0; it < P7_GPW; it++) {
        const int g = gwarp * P7_GPW + it;
        const float4* __restrict__ p = (const float4*)f + (size_t)g * 49;

        float a0 = 0.f, a1 = 0.f, a2 = 0.f, a3 = 0.f;
        #pragma unroll
        for (int rep = 0; rep < 2; rep++) {
            const int i = lane + rep * 32;
            if (i < 49) {
                float4 v = p[i];
                const int e = 4 * i;
                {
                    int pl = e / 49; float x = v.x;
                    if (pl == 0) a0 += x; else if (pl == 1) a1 += x;
                    else if (pl == 2) a2 += x; else a3 += x;
                }
                {
                    int pl = (e + 1) / 49; float x = v.y;
                    if (pl == 0) a0 += x; else if (pl == 1) a1 += x;
                    else if (pl == 2) a2 += x; else a3 += x;
                }
                {
                    int pl = (e + 2) / 49; float x = v.z;
                    if (pl == 0) a0 += x; else if (pl == 1) a1 += x;
                    else if (pl == 2) a2 += x; else a3 += x;
                }
                {
                    int pl = (e + 3) / 49; float x = v.w;
                    if (pl == 0) a0 += x; else if (pl == 1) a1 += x;
                    else if (pl == 2) a2 += x; else a3 += x;
                }
            }
        }
        #pragma unroll
        for (int o = 16; o > 0; o >>= 1) {
            a0 += __shfl_down_sync(0xFFFFFFFFu, a0, o);
            a1 += __shfl_down_sync(0xFFFFFFFFu, a1, o);
            a2 += __shfl_down_sync(0xFFFFFFFFu, a2, o);
            a3 += __shfl_down_sync(0xFFFFFFFFu, a3, o);
        }
        if (lane == 0) {
            const int plane0 = g * 4;
            #pragma unroll
            for (int k = 0; k < 4; k++) {
                const int plane = plane0 + k;
                const int b = plane >> 11;         // C = 2048
                const int c = plane & 2047;
                float ak = (k == 0) ? a0 : (k == 1) ? a1 : (k == 2) ? a2 : a3;
                g_v[b * CTOT + c_off + c] = ak * scale;
            }
        }
    }
}

// ---------------------------------------------------------------------------
// GEMM: out[32,1024] += v[32,3840] @ W[1024,3840]^T. Split-K with atomics.
// Tile: 32 b x 64 e; thread microtile 2b x 4e. Grid (16, 30), chunk K=128.
// ---------------------------------------------------------------------------
#define GEMM_ETILE  64
#define GEMM_KC     32
#define GEMM_KCHUNK 128
#define GEMM_KSPLIT 30

__global__ __launch_bounds__(256)
void gemm_kernel(const float* __restrict__ w, float* __restrict__ out) {
    __shared__ float vs[BATCH][GEMM_KC + 1];
    __shared__ float ws[GEMM_ETILE][GEMM_KC + 1];

    const int tid   = threadIdx.x;
    const int e0    = blockIdx.x * GEMM_ETILE;
    const int k0    = blockIdx.y * GEMM_KCHUNK;
    const int e_sub = tid & 15;
    const int b_sub = tid >> 4;

    float acc[2][4];
    #pragma unroll
    for (int i = 0; i < 2; i++)
        #pragma unroll
        for (int j = 0; j < 4; j++) acc[i][j] = 0.f;

    #pragma unroll
    for (int kc = 0; kc < GEMM_KCHUNK; kc += GEMM_KC) {
        const int kbase = k0 + kc;

        // v chunk: 32 rows x 32 k = 256 float4, one per thread
        {
            const int b  = tid >> 3;          // 0..31
            const int kq = tid & 7;           // 0..7
            float4 v4 = *(const float4*)&g_v[b * CTOT + kbase + 4 * kq];
            vs[b][4 * kq + 0] = v4.x;
            vs[b][4 * kq + 1] = v4.y;
            vs[b][4 * kq + 2] = v4.z;
            vs[b][4 * kq + 3] = v4.w;
        }
        // w chunk: 64 rows x 32 k = 512 float4, two per thread
        #pragma unroll
        for (int r = 0; r < 2; r++) {
            const int id = tid + r * 256;
            const int e  = id >> 3;
            const int kq = id & 7;
            float4 w4 = *(const float4*)&w[(size_t)(e0 + e) * CTOT + kbase + 4 * kq];
            ws[e][4 * kq + 0] = w4.x;
            ws[e][4 * kq + 1] = w4.y;
            ws[e][4 * kq + 2] = w4.z;
            ws[e][4 * kq + 3] = w4.w;
        }
        __syncthreads();

        #pragma unroll
        for (int kk = 0; kk < GEMM_KC; kk++) {
            float a0 = vs[2 * b_sub + 0][kk];
            float a1 = vs[2 * b_sub + 1][kk];
            float w0 = ws[4 * e_sub + 0][kk];
            float w1 = ws[4 * e_sub + 1][kk];
            float w2 = ws[4 * e_sub + 2][kk];
            float w3 = ws[4 * e_sub + 3][kk];
            acc[0][0] += a0 * w0; acc[0][1] += a0 * w1;
            acc[0][2] += a0 * w2; acc[0][3] += a0 * w3;
            acc[1][0] += a1 * w0; acc[1][1] += a1 * w1;
            acc[1][2] += a1 * w2; acc[1][3] += a1 * w3;
        }
        __syncthreads();
    }

    #pragma unroll
    for (int i = 0; i < 2; i++) {
        const int b = 2 * b_sub + i;
        #pragma unroll
        for (int j = 0; j < 4; j++) {
            const int e = e0 + 4 * e_sub + j;
            atomicAdd(&out[b * EMB + e], acc[i][j]);
        }
    }
}

// ---------------------------------------------------------------------------
extern "C" void kernel_launch(void* const* d_in, const int* in_sizes, int n_in,
                              void* d_out, int out_size) {
    const float* feat0  = (const float*)d_in[0];
    const float* feat1  = (const float*)d_in[1];
    const float* feat2  = (const float*)d_in[2];
    const float* feat3  = (const float*)d_in[3];
    const float* conv_w = (const float*)d_in[4];
    float* out = (float*)d_out;

    // Level 0: 8192 planes, 784 f4 each. 2 planes/warp -> 4096 warps -> 512 blocks
    pool_warp_kernel<784, 2, 8 /*C=256*/><<<512, 256>>>(feat0, 0, 1.f / 3136.f);
    // Level 1: 16384 planes, 196 f4. 4 planes/warp -> 512 blocks
    pool_warp_kernel<196, 4, 9 /*C=512*/><<<512, 256>>>(feat1, 256, 1.f / 784.f);
    // Level 2: 32768 planes, 49 f4. 8 planes/warp -> 512 blocks
    pool_warp_kernel<49, 8, 10 /*C=1024*/><<<512, 256>>>(feat2, 768, 1.f / 196.f);
    // Level 3: 65536 planes -> 16384 groups of 4. 8 groups/warp -> 256 blocks
    pool7_kernel<<<256, 256>>>(feat3, 1792, 1.f / 49.f);

    cudaMemsetAsync(d_out, 0, (size_t)out_size * sizeof(float), 0);

    dim3 grid(EMB / GEMM_ETILE, GEMM_KSPLIT);
    gemm_kernel<<<grid, 256>>>(conv_w, out);
}

// round 3
// speedup vs baseline: 2.9676x; 1.3449x over previous
#include <cuda_runtime.h>
#include <cuda_bf16.h>

// ---------------------------------------------------------------------------
// out[32,1024] = concat_c( spatial_mean(feat_l) ) @ conv_w.T
// (bilinear half-pixel upsample at ratios 1,2,4,8 + mean == plain mean; the
//  triangle-kernel edge renormalization makes per-source weights exactly
//  uniform.)
// feat0 [32,256,56,56], feat1 [32,512,28,28], feat2 [32,1024,14,14],
// feat3 [32,2048,7,7], conv_w [1024,3840].
// ---------------------------------------------------------------------------

#define BATCH 32
#define CTOT  3840
#define EMB   1024

__device__ float g_v[BATCH * CTOT];   // pooled vector [32,3840]

__device__ __forceinline__ float warp_reduce(float s) {
    #pragma unroll
    for (int o = 16; o > 0; o >>= 1)
        s += __shfl_down_sync(0xFFFFFFFFu, s, o);
    return s;
}

// ---------------------------------------------------------------------------
// Fused pooling kernel. Block ranges:
//   [0,1024):    lvl0, 1 plane/warp   (784 f4/plane, C=256)
//   [1024,2048): lvl1, 2 planes/warp  (196 f4/plane, C=512)
//   [2048,4096): lvl2, 2 planes/warp  ( 49 f4/plane, C=1024)
//   [4096,6144): lvl3, 1 group of 4 planes/warp (49 f4/group, C=2048)
// ---------------------------------------------------------------------------
#define NBLK0 1024
#define NBLK1 1024
#define NBLK2 2048
#define NBLK3 2048
#define NBLK_TOTAL (NBLK0 + NBLK1 + NBLK2 + NBLK3)

__global__ __launch_bounds__(256)
void fused_pool_kernel(const float* __restrict__ f0,
                       const float* __restrict__ f1,
                       const float* __restrict__ f2,
                       const float* __restrict__ f3) {
    const int blk  = blockIdx.x;
    const int lane = threadIdx.x & 31;
    const int warp = threadIdx.x >> 5;

    if (blk < NBLK0) {
        // ------- level 0: 56x56 = 784 f4, warp per plane -------
        const int plane = blk * 8 + warp;                 // 8192 planes
        const float4* __restrict__ p = (const float4*)f0 + (size_t)plane * 784;
        float a0 = 0.f, a1 = 0.f, a2 = 0.f, a3 = 0.f;
        #pragma unroll
        for (int k = 0; k < 6; k++) {
            float4 v0 = p[lane + (4 * k + 0) * 32];
            float4 v1 = p[lane + (4 * k + 1) * 32];
            float4 v2 = p[lane + (4 * k + 2) * 32];
            float4 v3 = p[lane + (4 * k + 3) * 32];
            a0 += (v0.x + v0.y) + (v0.z + v0.w);
            a1 += (v1.x + v1.y) + (v1.z + v1.w);
            a2 += (v2.x + v2.y) + (v2.z + v2.w);
            a3 += (v3.x + v3.y) + (v3.z + v3.w);
        }
        if (lane < 16) {                                   // 784 = 24*32 + 16
            float4 v = p[768 + lane];
            a0 += (v.x + v.y) + (v.z + v.w);
        }
        float s = warp_reduce((a0 + a1) + (a2 + a3));
        if (lane == 0) {
            const int b = plane >> 8, c = plane & 255;
            g_v[b * CTOT + c] = s * (1.f / 3136.f);
        }
    } else if (blk < NBLK0 + NBLK1) {
        // ------- level 1: 28x28 = 196 f4, 2 planes per warp -------
        const int g = (blk - NBLK0) * 8 + warp;            // 8192 pairs
        const int plane0 = g * 2;
        const float4* __restrict__ p = (const float4*)f1 + (size_t)plane0 * 196;
        float s0 = 0.f, s1 = 0.f;
        #pragma unroll
        for (int k = 0; k < 6; k++) {
            float4 v0 = p[lane + k * 32];
            float4 v1 = p[196 + lane + k * 32];
            s0 += (v0.x + v0.y) + (v0.z + v0.w);
            s1 += (v1.x + v1.y) + (v1.z + v1.w);
        }
        if (lane < 4) {                                    // 196 = 6*32 + 4
            float4 v0 = p[192 + lane];
            float4 v1 = p[196 + 192 + lane];
            s0 += (v0.x + v0.y) + (v0.z + v0.w);
            s1 += (v1.x + v1.y) + (v1.z + v1.w);
        }
        s0 = warp_reduce(s0);
        s1 = warp_reduce(s1);
        if (lane == 0) {
            const int b = plane0 >> 9, c = plane0 & 511;   // C=512
            g_v[b * CTOT + 256 + c]     = s0 * (1.f / 784.f);
            g_v[b * CTOT + 256 + c + 1] = s1 * (1.f / 784.f);
        }
    } else if (blk < NBLK0 + NBLK1 + NBLK2) {
        // ------- level 2: 14x14 = 49 f4, 2 planes per warp -------
        const int g = (blk - NBLK0 - NBLK1) * 8 + warp;    // 16384 pairs
        const int plane0 = g * 2;
        const float4* __restrict__ p = (const float4*)f2 + (size_t)plane0 * 49;
        float s0, s1;
        {
            float4 v0 = p[lane];
            float4 v1 = p[49 + lane];
            s0 = (v0.x + v0.y) + (v0.z + v0.w);
            s1 = (v1.x + v1.y) + (v1.z + v1.w);
        }
        if (lane < 17) {                                   // 49 = 32 + 17
            float4 v0 = p[32 + lane];
            float4 v1 = p[49 + 32 + lane];
            s0 += (v0.x + v0.y) + (v0.z + v0.w);
            s1 += (v1.x + v1.y) + (v1.z + v1.w);
        }
        s0 = warp_reduce(s0);
        s1 = warp_reduce(s1);
        if (lane == 0) {
            const int b = plane0 >> 10, c = plane0 & 1023; // C=1024
            g_v[b * CTOT + 768 + c]     = s0 * (1.f / 196.f);
            g_v[b * CTOT + 768 + c + 1] = s1 * (1.f / 196.f);
        }
    } else {
        // ------- level 3: 7x7 planes; 4 planes = 49 f4 per warp -------
        const int g = (blk - NBLK0 - NBLK1 - NBLK2) * 8 + warp;  // 16384 groups
        const float4* __restrict__ p = (const float4*)f3 + (size_t)g * 49;

        float a0 = 0.f, a1 = 0.f, a2 = 0.f, a3 = 0.f;
        #pragma unroll
        for (int rep = 0; rep < 2; rep++) {
            const int i = lane + rep * 32;
            if (i < 49) {
                float4 v = p[i];
                const int e = 4 * i;
                {
                    int pl = e / 49; float x = v.x;
                    if (pl == 0) a0 += x; else if (pl == 1) a1 += x;
                    else if (pl == 2) a2 += x; else a3 += x;
                }
                {
                    int pl = (e + 1) / 49; float x = v.y;
                    if (pl == 0) a0 += x; else if (pl == 1) a1 += x;
                    else if (pl == 2) a2 += x; else a3 += x;
                }
                {
                    int pl = (e + 2) / 49; float x = v.z;
                    if (pl == 0) a0 += x; else if (pl == 1) a1 += x;
                    else if (pl == 2) a2 += x; else a3 += x;
                }
                {
                    int pl = (e + 3) / 49; float x = v.w;
                    if (pl == 0) a0 += x; else if (pl == 1) a1 += x;
                    else if (pl == 2) a2 += x; else a3 += x;
                }
            }
        }
        a0 = warp_reduce(a0);
        a1 = warp_reduce(a1);
        a2 = warp_reduce(a2);
        a3 = warp_reduce(a3);
        if (lane == 0) {
            const int plane0 = g * 4;
            const int b = plane0 >> 11, c = plane0 & 2047; // C=2048
            float* dst = &g_v[b * CTOT + 1792 + c];
            dst[0] = a0 * (1.f / 49.f);
            dst[1] = a1 * (1.f / 49.f);
            dst[2] = a2 * (1.f / 49.f);
            dst[3] = a3 * (1.f / 49.f);
        }
    }
}

// ---------------------------------------------------------------------------
// GEMM: out[32,1024] += v[32,3840] @ W[1024,3840]^T. Split-K with atomics.
// ---------------------------------------------------------------------------
#define GEMM_ETILE  64
#define GEMM_KC     32
#define GEMM_KCHUNK 128
#define GEMM_KSPLIT 30

__global__ __launch_bounds__(256)
void gemm_kernel(const float* __restrict__ w, float* __restrict__ out) {
    __shared__ float vs[BATCH][GEMM_KC + 1];
    __shared__ float ws[GEMM_ETILE][GEMM_KC + 1];

    const int tid   = threadIdx.x;
    const int e0    = blockIdx.x * GEMM_ETILE;
    const int k0    = blockIdx.y * GEMM_KCHUNK;
    const int e_sub = tid & 15;
    const int b_sub = tid >> 4;

    float acc[2][4];
    #pragma unroll
    for (int i = 0; i < 2; i++)
        #pragma unroll
        for (int j = 0; j < 4; j++) acc[i][j] = 0.f;

    #pragma unroll
    for (int kc = 0; kc < GEMM_KCHUNK; kc += GEMM_KC) {
        const int kbase = k0 + kc;
        {
            const int b  = tid >> 3;
            const int kq = tid & 7;
            float4 v4 = *(const float4*)&g_v[b * CTOT + kbase + 4 * kq];
            vs[b][4 * kq + 0] = v4.x;
            vs[b][4 * kq + 1] = v4.y;
            vs[b][4 * kq + 2] = v4.z;
            vs[b][4 * kq + 3] = v4.w;
        }
        #pragma unroll
        for (int r = 0; r < 2; r++) {
            const int id = tid + r * 256;
            const int e  = id >> 3;
            const int kq = id & 7;
            float4 w4 = *(const float4*)&w[(size_t)(e0 + e) * CTOT + kbase + 4 * kq];
            ws[e][4 * kq + 0] = w4.x;
            ws[e][4 * kq + 1] = w4.y;
            ws[e][4 * kq + 2] = w4.z;
            ws[e][4 * kq + 3] = w4.w;
        }
        __syncthreads();

        #pragma unroll
        for (int kk = 0; kk < GEMM_KC; kk++) {
            float a0 = vs[2 * b_sub + 0][kk];
            float a1 = vs[2 * b_sub + 1][kk];
            float w0 = ws[4 * e_sub + 0][kk];
            float w1 = ws[4 * e_sub + 1][kk];
            float w2 = ws[4 * e_sub + 2][kk];
            float w3 = ws[4 * e_sub + 3][kk];
            acc[0][0] += a0 * w0; acc[0][1] += a0 * w1;
            acc[0][2] += a0 * w2; acc[0][3] += a0 * w3;
            acc[1][0] += a1 * w0; acc[1][1] += a1 * w1;
            acc[1][2] += a1 * w2; acc[1][3] += a1 * w3;
        }
        __syncthreads();
    }

    #pragma unroll
    for (int i = 0; i < 2; i++) {
        const int b = 2 * b_sub + i;
        #pragma unroll
        for (int j = 0; j < 4; j++) {
            const int e = e0 + 4 * e_sub + j;
            atomicAdd(&out[b * EMB + e], acc[i][j]);
        }
    }
}

// ---------------------------------------------------------------------------
extern "C" void kernel_launch(void* const* d_in, const int* in_sizes, int n_in,
                              void* d_out, int out_size) {
    const float* feat0  = (const float*)d_in[0];
    const float* feat1  = (const float*)d_in[1];
    const float* feat2  = (const float*)d_in[2];
    const float* feat3  = (const float*)d_in[3];
    const float* conv_w = (const float*)d_in[4];
    float* out = (float*)d_out;

    fused_pool_kernel<<<NBLK_TOTAL, 256>>>(feat0, feat1, feat2, feat3);

    cudaMemsetAsync(d_out, 0, (size_t)out_size * sizeof(float), 0);

    dim3 grid(EMB / GEMM_ETILE, GEMM_KSPLIT);
    gemm_kernel<<<grid, 256>>>(conv_w, out);
}

// round 4
// speedup vs baseline: 3.0651x; 1.0328x over previous
#include <cuda_runtime.h>
#include <cuda_bf16.h>

// ---------------------------------------------------------------------------
// out[32,1024] = concat_c( spatial_mean(feat_l) ) @ conv_w.T
// (bilinear half-pixel upsample at ratios 1,2,4,8 + mean == plain mean.)
// feat0 [32,256,56,56], feat1 [32,512,28,28], feat2 [32,1024,14,14],
// feat3 [32,2048,7,7], conv_w [1024,3840].
// ---------------------------------------------------------------------------

#define BATCH 32
#define CTOT  3840
#define EMB   1024

__device__ float g_v[BATCH * CTOT];   // pooled vector [32,3840]

__device__ __forceinline__ float warp_reduce(float s) {
    #pragma unroll
    for (int o = 16; o > 0; o >>= 1)
        s += __shfl_down_sync(0xFFFFFFFFu, s, o);
    return s;
}

// ---------------------------------------------------------------------------
// Fused pooling kernel (unchanged from R3 — at HBM roofline).
// ---------------------------------------------------------------------------
#define NBLK0 1024
#define NBLK1 1024
#define NBLK2 2048
#define NBLK3 2048
#define NBLK_TOTAL (NBLK0 + NBLK1 + NBLK2 + NBLK3)

__global__ __launch_bounds__(256)
void fused_pool_kernel(const float* __restrict__ f0,
                       const float* __restrict__ f1,
                       const float* __restrict__ f2,
                       const float* __restrict__ f3) {
    const int blk  = blockIdx.x;
    const int lane = threadIdx.x & 31;
    const int warp = threadIdx.x >> 5;

    if (blk < NBLK0) {
        const int plane = blk * 8 + warp;
        const float4* __restrict__ p = (const float4*)f0 + (size_t)plane * 784;
        float a0 = 0.f, a1 = 0.f, a2 = 0.f, a3 = 0.f;
        #pragma unroll
        for (int k = 0; k < 6; k++) {
            float4 v0 = p[lane + (4 * k + 0) * 32];
            float4 v1 = p[lane + (4 * k + 1) * 32];
            float4 v2 = p[lane + (4 * k + 2) * 32];
            float4 v3 = p[lane + (4 * k + 3) * 32];
            a0 += (v0.x + v0.y) + (v0.z + v0.w);
            a1 += (v1.x + v1.y) + (v1.z + v1.w);
            a2 += (v2.x + v2.y) + (v2.z + v2.w);
            a3 += (v3.x + v3.y) + (v3.z + v3.w);
        }
        if (lane < 16) {
            float4 v = p[768 + lane];
            a0 += (v.x + v.y) + (v.z + v.w);
        }
        float s = warp_reduce((a0 + a1) + (a2 + a3));
        if (lane == 0) {
            const int b = plane >> 8, c = plane & 255;
            g_v[b * CTOT + c] = s * (1.f / 3136.f);
        }
    } else if (blk < NBLK0 + NBLK1) {
        const int g = (blk - NBLK0) * 8 + warp;
        const int plane0 = g * 2;
        const float4* __restrict__ p = (const float4*)f1 + (size_t)plane0 * 196;
        float s0 = 0.f, s1 = 0.f;
        #pragma unroll
        for (int k = 0; k < 6; k++) {
            float4 v0 = p[lane + k * 32];
            float4 v1 = p[196 + lane + k * 32];
            s0 += (v0.x + v0.y) + (v0.z + v0.w);
            s1 += (v1.x + v1.y) + (v1.z + v1.w);
        }
        if (lane < 4) {
            float4 v0 = p[192 + lane];
            float4 v1 = p[196 + 192 + lane];
            s0 += (v0.x + v0.y) + (v0.z + v0.w);
            s1 += (v1.x + v1.y) + (v1.z + v1.w);
        }
        s0 = warp_reduce(s0);
        s1 = warp_reduce(s1);
        if (lane == 0) {
            const int b = plane0 >> 9, c = plane0 & 511;
            g_v[b * CTOT + 256 + c]     = s0 * (1.f / 784.f);
            g_v[b * CTOT + 256 + c + 1] = s1 * (1.f / 784.f);
        }
    } else if (blk < NBLK0 + NBLK1 + NBLK2) {
        const int g = (blk - NBLK0 - NBLK1) * 8 + warp;
        const int plane0 = g * 2;
        const float4* __restrict__ p = (const float4*)f2 + (size_t)plane0 * 49;
        float s0, s1;
        {
            float4 v0 = p[lane];
            float4 v1 = p[49 + lane];
            s0 = (v0.x + v0.y) + (v0.z + v0.w);
            s1 = (v1.x + v1.y) + (v1.z + v1.w);
        }
        if (lane < 17) {
            float4 v0 = p[32 + lane];
            float4 v1 = p[49 + 32 + lane];
            s0 += (v0.x + v0.y) + (v0.z + v0.w);
            s1 += (v1.x + v1.y) + (v1.z + v1.w);
        }
        s0 = warp_reduce(s0);
        s1 = warp_reduce(s1);
        if (lane == 0) {
            const int b = plane0 >> 10, c = plane0 & 1023;
            g_v[b * CTOT + 768 + c]     = s0 * (1.f / 196.f);
            g_v[b * CTOT + 768 + c + 1] = s1 * (1.f / 196.f);
        }
    } else {
        const int g = (blk - NBLK0 - NBLK1 - NBLK2) * 8 + warp;
        const float4* __restrict__ p = (const float4*)f3 + (size_t)g * 49;

        float a0 = 0.f, a1 = 0.f, a2 = 0.f, a3 = 0.f;
        #pragma unroll
        for (int rep = 0; rep < 2; rep++) {
            const int i = lane + rep * 32;
            if (i < 49) {
                float4 v = p[i];
                const int e = 4 * i;
                {
                    int pl = e / 49; float x = v.x;
                    if (pl == 0) a0 += x; else if (pl == 1) a1 += x;
                    else if (pl == 2) a2 += x; else a3 += x;
                }
                {
                    int pl = (e + 1) / 49; float x = v.y;
                    if (pl == 0) a0 += x; else if (pl == 1) a1 += x;
                    else if (pl == 2) a2 += x; else a3 += x;
                }
                {
                    int pl = (e + 2) / 49; float x = v.z;
                    if (pl == 0) a0 += x; else if (pl == 1) a1 += x;
                    else if (pl == 2) a2 += x; else a3 += x;
                }
                {
                    int pl = (e + 3) / 49; float x = v.w;
                    if (pl == 0) a0 += x; else if (pl == 1) a1 += x;
                    else if (pl == 2) a2 += x; else a3 += x;
                }
            }
        }
        a0 = warp_reduce(a0);
        a1 = warp_reduce(a1);
        a2 = warp_reduce(a2);
        a3 = warp_reduce(a3);
        if (lane == 0) {
            const int plane0 = g * 4;
            const int b = plane0 >> 11, c = plane0 & 2047;
            float* dst = &g_v[b * CTOT + 1792 + c];
            dst[0] = a0 * (1.f / 49.f);
            dst[1] = a1 * (1.f / 49.f);
            dst[2] = a2 * (1.f / 49.f);
            dst[3] = a3 * (1.f / 49.f);
        }
    }
}

// ---------------------------------------------------------------------------
// GEMM v3: out[32,1024] += v @ W^T. Transposed smem (LDS.128 inner loop),
// 4b x 4e microtile, software-pipelined double buffer, split-K atomics.
// Tile: 32 b x 128 e, KCHUNK=128 in 4 chunks of KC=32. Grid (8, 30).
// ---------------------------------------------------------------------------
#define GEMM_ETILE  128
#define GEMM_KC     32
#define GEMM_NCHUNK 4
#define GEMM_KSPLIT 30

__global__ __launch_bounds__(256)
void gemm_kernel(const float* __restrict__ w, float* __restrict__ out) {
    // transposed: [buf][kk][e or b]
    __shared__ float ws[2][GEMM_KC][GEMM_ETILE];
    __shared__ float vs[2][GEMM_KC][BATCH];

    const int tid   = threadIdx.x;
    const int e0    = blockIdx.x * GEMM_ETILE;
    const int k0    = blockIdx.y * (GEMM_KC * GEMM_NCHUNK);

    // load indices (per chunk): v is 32b x 32k = 256 f4 (1/thread),
    // w is 128e x 32k = 1024 f4 (4/thread)
    const int vb = tid >> 3;          // 0..31
    const int vk = (tid & 7) * 4;     // 0,4,..,28
    const int we = tid >> 1;          // 0..127  (2 f4 per row chunk? no:)
    // w: id = tid + r*256, e = id>>1, kq = (id&1)*16? -> use e=id>>2? choose:
    // 1024 f4: id in [0,1024): e = id >> 3 (0..127), k4 = (id & 7)*4

    // compute indices: microtile 4b x 4e
    const int b_sub = (tid >> 5) * 4;   // warp id * 4 -> b0 (0..28)
    const int e_sub = (tid & 31) * 4;   // lane * 4 -> e  (0..124)

    float acc[4][4];
    #pragma unroll
    for (int i = 0; i < 4; i++)
        #pragma unroll
        for (int j = 0; j < 4; j++) acc[i][j] = 0.f;

    float4 pv;        // prefetched v
    float4 pw[4];     // prefetched w

    // --- prefetch chunk 0 ---
    {
        const int kb = k0;
        pv = *(const float4*)&g_v[vb * CTOT + kb + vk];
        #pragma unroll
        for (int r = 0; r < 4; r++) {
            const int id = tid + r * 256;
            const int e  = id >> 3;
            const int k4 = (id & 7) * 4;
            pw[r] = *(const float4*)&w[(size_t)(e0 + e) * CTOT + kb + k4];
        }
    }

    #pragma unroll
    for (int c = 0; c < GEMM_NCHUNK; c++) {
        const int buf = c & 1;

        // store prefetched chunk to smem (transposed)
        vs[buf][vk + 0][vb] = pv.x;
        vs[buf][vk + 1][vb] = pv.y;
        vs[buf][vk + 2][vb] = pv.z;
        vs[buf][vk + 3][vb] = pv.w;
        #pragma unroll
        for (int r = 0; r < 4; r++) {
            const int id = tid + r * 256;
            const int e  = id >> 3;
            const int k4 = (id & 7) * 4;
            ws[buf][k4 + 0][e] = pw[r].x;
            ws[buf][k4 + 1][e] = pw[r].y;
            ws[buf][k4 + 2][e] = pw[r].z;
            ws[buf][k4 + 3][e] = pw[r].w;
        }
        __syncthreads();

        // prefetch next chunk while computing this one
        if (c + 1 < GEMM_NCHUNK) {
            const int kb = k0 + (c + 1) * GEMM_KC;
            pv = *(const float4*)&g_v[vb * CTOT + kb + vk];
            #pragma unroll
            for (int r = 0; r < 4; r++) {
                const int id = tid + r * 256;
                const int e  = id >> 3;
                const int k4 = (id & 7) * 4;
                pw[r] = *(const float4*)&w[(size_t)(e0 + e) * CTOT + kb + k4];
            }
        }

        #pragma unroll
        for (int kk = 0; kk < GEMM_KC; kk++) {
            float4 av = *(const float4*)&vs[buf][kk][b_sub];  // warp-broadcast
            float4 wv = *(const float4*)&ws[buf][kk][e_sub];  // conflict-free
            acc[0][0] += av.x * wv.x; acc[0][1] += av.x * wv.y;
            acc[0][2] += av.x * wv.z; acc[0][3] += av.x * wv.w;
            acc[1][0] += av.y * wv.x; acc[1][1] += av.y * wv.y;
            acc[1][2] += av.y * wv.z; acc[1][3] += av.y * wv.w;
            acc[2][0] += av.z * wv.x; acc[2][1] += av.z * wv.y;
            acc[2][2] += av.z * wv.z; acc[2][3] += av.z * wv.w;
            acc[3][0] += av.w * wv.x; acc[3][1] += av.w * wv.y;
            acc[3][2] += av.w * wv.z; acc[3][3] += av.w * wv.w;
        }
        __syncthreads();
    }

    #pragma unroll
    for (int i = 0; i < 4; i++) {
        const int b = b_sub + i;
        #pragma unroll
        for (int j = 0; j < 4; j++) {
            atomicAdd(&out[b * EMB + e0 + e_sub + j], acc[i][j]);
        }
    }
}

// ---------------------------------------------------------------------------
extern "C" void kernel_launch(void* const* d_in, const int* in_sizes, int n_in,
                              void* d_out, int out_size) {
    const float* feat0  = (const float*)d_in[0];
    const float* feat1  = (const float*)d_in[1];
    const float* feat2  = (const float*)d_in[2];
    const float* feat3  = (const float*)d_in[3];
    const float* conv_w = (const float*)d_in[4];
    float* out = (float*)d_out;

    cudaMemsetAsync(d_out, 0, (size_t)out_size * sizeof(float), 0);

    fused_pool_kernel<<<NBLK_TOTAL, 256>>>(feat0, feat1, feat2, feat3);

    dim3 grid(EMB / GEMM_ETILE, GEMM_KSPLIT);
    gemm_kernel<<<grid, 256>>>(conv_w, out);
}

// round 7
// speedup vs baseline: 3.3562x; 1.0950x over previous
#include <cuda_runtime.h>
#include <cuda_bf16.h>
#include <cstdint>

// ---------------------------------------------------------------------------
// out[32,1024] = concat_c( spatial_mean(feat_l) ) @ conv_w.T
// (bilinear half-pixel upsample at ratios 1,2,4,8 + mean == plain mean; the
//  triangle-kernel edge renormalization makes per-source weights exactly
//  uniform.)
// feat0 [32,256,56,56], feat1 [32,512,28,28], feat2 [32,1024,14,14],
// feat3 [32,2048,7,7], conv_w [1024,3840].
//
// Two sequential kernels on the capture stream (no multi-stream tricks):
//  1) fused pool (proven at ~6 TB/s), 2) one-shot GEMM: whole W tile via
//  cp.async with full MLP, single wait, conflict-free pitch-132 smem.
// ---------------------------------------------------------------------------

#define BATCH 32
#define CTOT  3840
#define EMB   1024

__device__ float g_v[BATCH * CTOT];   // pooled vector [32,3840]

__device__ __forceinline__ float warp_reduce(float s) {
    #pragma unroll
    for (int o = 16; o > 0; o >>= 1)
        s += __shfl_down_sync(0xFFFFFFFFu, s, o);
    return s;
}

// ---------------------------------------------------------------------------
// Fused pooling kernel (R3 version — at HBM roofline).
// ---------------------------------------------------------------------------
#define NBLK0 1024
#define NBLK1 1024
#define NBLK2 2048
#define NBLK3 2048
#define NBLK_TOTAL (NBLK0 + NBLK1 + NBLK2 + NBLK3)

__global__ __launch_bounds__(256)
void fused_pool_kernel(const float* __restrict__ f0,
                       const float* __restrict__ f1,
                       const float* __restrict__ f2,
                       const float* __restrict__ f3) {
    const int blk  = blockIdx.x;
    const int lane = threadIdx.x & 31;
    const int warp = threadIdx.x >> 5;

    if (blk < NBLK0) {
        // ---- level 0: 56x56 = 784 f4, 1 plane per warp ----
        const int plane = blk * 8 + warp;
        const float4* __restrict__ p = (const float4*)f0 + (size_t)plane * 784;
        float a0 = 0.f, a1 = 0.f, a2 = 0.f, a3 = 0.f;
        #pragma unroll
        for (int k = 0; k < 6; k++) {
            float4 v0 = p[lane + (4 * k + 0) * 32];
            float4 v1 = p[lane + (4 * k + 1) * 32];
            float4 v2 = p[lane + (4 * k + 2) * 32];
            float4 v3 = p[lane + (4 * k + 3) * 32];
            a0 += (v0.x + v0.y) + (v0.z + v0.w);
            a1 += (v1.x + v1.y) + (v1.z + v1.w);
            a2 += (v2.x + v2.y) + (v2.z + v2.w);
            a3 += (v3.x + v3.y) + (v3.z + v3.w);
        }
        if (lane < 16) {
            float4 v = p[768 + lane];
            a0 += (v.x + v.y) + (v.z + v.w);
        }
        float s = warp_reduce((a0 + a1) + (a2 + a3));
        if (lane == 0) {
            const int b = plane >> 8, c = plane & 255;      // C=256
            g_v[b * CTOT + c] = s * (1.f / 3136.f);
        }
    } else if (blk < NBLK0 + NBLK1) {
        // ---- level 1: 28x28 = 196 f4, 2 planes per warp ----
        const int g = (blk - NBLK0) * 8 + warp;
        const int plane0 = g * 2;
        const float4* __restrict__ p = (const float4*)f1 + (size_t)plane0 * 196;
        float s0 = 0.f, s1 = 0.f;
        #pragma unroll
        for (int k = 0; k < 6; k++) {
            float4 v0 = p[lane + k * 32];
            float4 v1 = p[196 + lane + k * 32];
            s0 += (v0.x + v0.y) + (v0.z + v0.w);
            s1 += (v1.x + v1.y) + (v1.z + v1.w);
        }
        if (lane < 4) {
            float4 v0 = p[192 + lane];
            float4 v1 = p[196 + 192 + lane];
            s0 += (v0.x + v0.y) + (v0.z + v0.w);
            s1 += (v1.x + v1.y) + (v1.z + v1.w);
        }
        s0 = warp_reduce(s0);
        s1 = warp_reduce(s1);
        if (lane == 0) {
            const int b = plane0 >> 9, c = plane0 & 511;    // C=512
            g_v[b * CTOT + 256 + c]     = s0 * (1.f / 784.f);
            g_v[b * CTOT + 256 + c + 1] = s1 * (1.f / 784.f);
        }
    } else if (blk < NBLK0 + NBLK1 + NBLK2) {
        // ---- level 2: 14x14 = 49 f4, 2 planes per warp ----
        const int g = (blk - NBLK0 - NBLK1) * 8 + warp;
        const int plane0 = g * 2;
        const float4* __restrict__ p = (const float4*)f2 + (size_t)plane0 * 49;
        float s0, s1;
        {
            float4 v0 = p[lane];
            float4 v1 = p[49 + lane];
            s0 = (v0.x + v0.y) + (v0.z + v0.w);
            s1 = (v1.x + v1.y) + (v1.z + v1.w);
        }
        if (lane < 17) {
            float4 v0 = p[32 + lane];
            float4 v1 = p[49 + 32 + lane];
            s0 += (v0.x + v0.y) + (v0.z + v0.w);
            s1 += (v1.x + v1.y) + (v1.z + v1.w);
        }
        s0 = warp_reduce(s0);
        s1 = warp_reduce(s1);
        if (lane == 0) {
            const int b = plane0 >> 10, c = plane0 & 1023;  // C=1024
            g_v[b * CTOT + 768 + c]     = s0 * (1.f / 196.f);
            g_v[b * CTOT + 768 + c + 1] = s1 * (1.f / 196.f);
        }
    } else {
        // ---- level 3: 7x7 planes; warp handles 4 planes = 49 f4 ----
        const int g = (blk - NBLK0 - NBLK1 - NBLK2) * 8 + warp;
        const float4* __restrict__ p = (const float4*)f3 + (size_t)g * 49;

        float a0 = 0.f, a1 = 0.f, a2 = 0.f, a3 = 0.f;
        #pragma unroll
        for (int rep = 0; rep < 2; rep++) {
            const int i = lane + rep * 32;
            if (i < 49) {
                float4 v = p[i];
                const int e = 4 * i;
                {
                    int pl = e / 49; float x = v.x;
                    if (pl == 0) a0 += x; else if (pl == 1) a1 += x;
                    else if (pl == 2) a2 += x; else a3 += x;
                }
                {
                    int pl = (e + 1) / 49; float x = v.y;
                    if (pl == 0) a0 += x; else if (pl == 1) a1 += x;
                    else if (pl == 2) a2 += x; else a3 += x;
                }
                {
                    int pl = (e + 2) / 49; float x = v.z;
                    if (pl == 0) a0 += x; else if (pl == 1) a1 += x;
                    else if (pl == 2) a2 += x; else a3 += x;
                }
                {
                    int pl = (e + 3) / 49; float x = v.w;
                    if (pl == 0) a0 += x; else if (pl == 1) a1 += x;
                    else if (pl == 2) a2 += x; else a3 += x;
                }
            }
        }
        a0 = warp_reduce(a0);
        a1 = warp_reduce(a1);
        a2 = warp_reduce(a2);
        a3 = warp_reduce(a3);
        if (lane == 0) {
            const int plane0 = g * 4;
            const int b = plane0 >> 11, c = plane0 & 2047;  // C=2048
            float* dst = &g_v[b * CTOT + 1792 + c];
            dst[0] = a0 * (1.f / 49.f);
            dst[1] = a1 * (1.f / 49.f);
            dst[2] = a2 * (1.f / 49.f);
            dst[3] = a3 * (1.f / 49.f);
        }
    }
}

// ---------------------------------------------------------------------------
// One-shot GEMM: grid (8 e-tiles, 30 k-splits), 128 threads.
// Per block: cp.async the whole 128e x 128k W tile (32 chunks/thread, full
// MLP), LDG the 32b x 128k v slice into smem meanwhile, single wait, compute
// 8b x 4e microtile over all 32 k4 steps, atomicAdd (split-K).
// smem rows pitch 132 floats -> LDS.128 conflict-free (8-lane phase covers
// 32 distinct banks: bank = 4*lane + o).
// ---------------------------------------------------------------------------
#define GEMM_KSPLIT 30
#define GEMM_SMEM ((128 * 132 + 32 * 132) * 4)

__global__ __launch_bounds__(128)
void gemm_kernel(const float* __restrict__ w, float* __restrict__ out) {
    extern __shared__ float sm[];
    float* ws = sm;                 // [128][132]
    float* vs = sm + 128 * 132;     // [32][132]

    const int e0  = blockIdx.x * 128;
    const int k0  = blockIdx.y * 128;
    const int tid = threadIdx.x;

    // --- cp.async entire W tile: 128 rows x 32 f4-chunks = 4096 chunks ---
    #pragma unroll
    for (int r = 0; r < 32; r++) {
        const int cid = tid + r * 128;
        const int e   = cid >> 5;
        const int kc  = cid & 31;
        const float* src = w + (size_t)(e0 + e) * CTOT + k0 + kc * 4;
        unsigned dst = (unsigned)__cvta_generic_to_shared(&ws[e * 132 + kc * 4]);
        asm volatile("cp.async.cg.shared.global [%0], [%1], 16;\n"
                     :: "r"(dst), "l"(src));
    }
    asm volatile("cp.async.commit_group;\n");

    // --- v slice: 32 rows x 32 chunks = 1024 f4, 8 per thread (L2-hot) ---
    #pragma unroll
    for (int r = 0; r < 8; r++) {
        const int i  = tid + r * 128;
        const int b  = i >> 5;
        const int kq = i & 31;
        float4 v4 = *(const float4*)&g_v[b * CTOT + k0 + kq * 4];
        *(float4*)&vs[b * 132 + kq * 4] = v4;
    }

    asm volatile("cp.async.wait_group 0;\n" ::: "memory");
    __syncthreads();

    // --- compute: microtile 8b x 4e ---
    const int lane = tid & 31;
    const int b0   = (tid >> 5) * 8;

    float acc[8][4];
    #pragma unroll
    for (int i = 0; i < 8; i++)
        #pragma unroll
        for (int j = 0; j < 4; j++) acc[i][j] = 0.f;

    #pragma unroll 4
    for (int k4 = 0; k4 < 32; k4++) {
        float4 wv[4];
        #pragma unroll
        for (int j = 0; j < 4; j++)
            wv[j] = *(const float4*)&ws[(lane + 32 * j) * 132 + k4 * 4];
        #pragma unroll
        for (int i = 0; i < 8; i++) {
            float4 av = *(const float4*)&vs[(b0 + i) * 132 + k4 * 4];
            #pragma unroll
            for (int j = 0; j < 4; j++)
                acc[i][j] += av.x * wv[j].x + av.y * wv[j].y
                           + av.z * wv[j].z + av.w * wv[j].w;
        }
    }

    #pragma unroll
    for (int i = 0; i < 8; i++) {
        const int b = b0 + i;
        #pragma unroll
        for (int j = 0; j < 4; j++)
            atomicAdd(&out[b * EMB + e0 + lane + 32 * j], acc[i][j]);
    }
}

// ---------------------------------------------------------------------------
extern "C" void kernel_launch(void* const* d_in, const int* in_sizes, int n_in,
                              void* d_out, int out_size) {
    const float* feat0  = (const float*)d_in[0];
    const float* feat1  = (const float*)d_in[1];
    const float* feat2  = (const float*)d_in[2];
    const float* feat3  = (const float*)d_in[3];
    const float* conv_w = (const float*)d_in[4];
    float* out = (float*)d_out;

    cudaFuncSetAttribute(gemm_kernel,
                         cudaFuncAttributeMaxDynamicSharedMemorySize, GEMM_SMEM);

    cudaMemsetAsync(d_out, 0, (size_t)out_size * sizeof(float), 0);

    fused_pool_kernel<<<NBLK_TOTAL, 256>>>(feat0, feat1, feat2, feat3);

    dim3 grid(EMB / 128, GEMM_KSPLIT);
    gemm_kernel<<<grid, 128, GEMM_SMEM>>>(conv_w, out);
}

// round 8
// speedup vs baseline: 3.3653x; 1.0027x over previous
#include <cuda_runtime.h>
#include <cuda_bf16.h>
#include <cstdint>

// ---------------------------------------------------------------------------
// out[32,1024] = concat_c( spatial_mean(feat_l) ) @ conv_w.T
// (bilinear half-pixel upsample at ratios 1,2,4,8 + mean == plain mean.)
// feat0 [32,256,56,56], feat1 [32,512,28,28], feat2 [32,1024,14,14],
// feat3 [32,2048,7,7], conv_w [1024,3840].
//
// Pool: fused warp-per-plane kernel at HBM roofline (~6.2 TB/s).
// GEMM: fp32 FFMA-pipe bound -> use packed fma.rn.f32x2 (sm_103a), packing
// along K (even/odd partial sums), exact fp32 math, 2x fma throughput.
// ---------------------------------------------------------------------------

#define BATCH 32
#define CTOT  3840
#define EMB   1024

__device__ float g_v[BATCH * CTOT];   // pooled vector [32,3840]

__device__ __forceinline__ float warp_reduce(float s) {
    #pragma unroll
    for (int o = 16; o > 0; o >>= 1)
        s += __shfl_down_sync(0xFFFFFFFFu, s, o);
    return s;
}

// ---------------------------------------------------------------------------
// Fused pooling kernel (unchanged — at HBM roofline).
// ---------------------------------------------------------------------------
#define NBLK0 1024
#define NBLK1 1024
#define NBLK2 2048
#define NBLK3 2048
#define NBLK_TOTAL (NBLK0 + NBLK1 + NBLK2 + NBLK3)

__global__ __launch_bounds__(256)
void fused_pool_kernel(const float* __restrict__ f0,
                       const float* __restrict__ f1,
                       const float* __restrict__ f2,
                       const float* __restrict__ f3) {
    const int blk  = blockIdx.x;
    const int lane = threadIdx.x & 31;
    const int warp = threadIdx.x >> 5;

    if (blk < NBLK0) {
        // ---- level 0: 56x56 = 784 f4, 1 plane per warp ----
        const int plane = blk * 8 + warp;
        const float4* __restrict__ p = (const float4*)f0 + (size_t)plane * 784;
        float a0 = 0.f, a1 = 0.f, a2 = 0.f, a3 = 0.f;
        #pragma unroll
        for (int k = 0; k < 6; k++) {
            float4 v0 = p[lane + (4 * k + 0) * 32];
            float4 v1 = p[lane + (4 * k + 1) * 32];
            float4 v2 = p[lane + (4 * k + 2) * 32];
            float4 v3 = p[lane + (4 * k + 3) * 32];
            a0 += (v0.x + v0.y) + (v0.z + v0.w);
            a1 += (v1.x + v1.y) + (v1.z + v1.w);
            a2 += (v2.x + v2.y) + (v2.z + v2.w);
            a3 += (v3.x + v3.y) + (v3.z + v3.w);
        }
        if (lane < 16) {
            float4 v = p[768 + lane];
            a0 += (v.x + v.y) + (v.z + v.w);
        }
        float s = warp_reduce((a0 + a1) + (a2 + a3));
        if (lane == 0) {
            const int b = plane >> 8, c = plane & 255;      // C=256
            g_v[b * CTOT + c] = s * (1.f / 3136.f);
        }
    } else if (blk < NBLK0 + NBLK1) {
        // ---- level 1: 28x28 = 196 f4, 2 planes per warp ----
        const int g = (blk - NBLK0) * 8 + warp;
        const int plane0 = g * 2;
        const float4* __restrict__ p = (const float4*)f1 + (size_t)plane0 * 196;
        float s0 = 0.f, s1 = 0.f;
        #pragma unroll
        for (int k = 0; k < 6; k++) {
            float4 v0 = p[lane + k * 32];
            float4 v1 = p[196 + lane + k * 32];
            s0 += (v0.x + v0.y) + (v0.z + v0.w);
            s1 += (v1.x + v1.y) + (v1.z + v1.w);
        }
        if (lane < 4) {
            float4 v0 = p[192 + lane];
            float4 v1 = p[196 + 192 + lane];
            s0 += (v0.x + v0.y) + (v0.z + v0.w);
            s1 += (v1.x + v1.y) + (v1.z + v1.w);
        }
        s0 = warp_reduce(s0);
        s1 = warp_reduce(s1);
        if (lane == 0) {
            const int b = plane0 >> 9, c = plane0 & 511;    // C=512
            g_v[b * CTOT + 256 + c]     = s0 * (1.f / 784.f);
            g_v[b * CTOT + 256 + c + 1] = s1 * (1.f / 784.f);
        }
    } else if (blk < NBLK0 + NBLK1 + NBLK2) {
        // ---- level 2: 14x14 = 49 f4, 2 planes per warp ----
        const int g = (blk - NBLK0 - NBLK1) * 8 + warp;
        const int plane0 = g * 2;
        const float4* __restrict__ p = (const float4*)f2 + (size_t)plane0 * 49;
        float s0, s1;
        {
            float4 v0 = p[lane];
            float4 v1 = p[49 + lane];
            s0 = (v0.x + v0.y) + (v0.z + v0.w);
            s1 = (v1.x + v1.y) + (v1.z + v1.w);
        }
        if (lane < 17) {
            float4 v0 = p[32 + lane];
            float4 v1 = p[49 + 32 + lane];
            s0 += (v0.x + v0.y) + (v0.z + v0.w);
            s1 += (v1.x + v1.y) + (v1.z + v1.w);
        }
        s0 = warp_reduce(s0);
        s1 = warp_reduce(s1);
        if (lane == 0) {
            const int b = plane0 >> 10, c = plane0 & 1023;  // C=1024
            g_v[b * CTOT + 768 + c]     = s0 * (1.f / 196.f);
            g_v[b * CTOT + 768 + c + 1] = s1 * (1.f / 196.f);
        }
    } else {
        // ---- level 3: 7x7 planes; warp handles 4 planes = 49 f4 ----
        const int g = (blk - NBLK0 - NBLK1 - NBLK2) * 8 + warp;
        const float4* __restrict__ p = (const float4*)f3 + (size_t)g * 49;

        float a0 = 0.f, a1 = 0.f, a2 = 0.f, a3 = 0.f;
        #pragma unroll
        for (int rep = 0; rep < 2; rep++) {
            const int i = lane + rep * 32;
            if (i < 49) {
                float4 v = p[i];
                const int e = 4 * i;
                {
                    int pl = e / 49; float x = v.x;
                    if (pl == 0) a0 += x; else if (pl == 1) a1 += x;
                    else if (pl == 2) a2 += x; else a3 += x;
                }
                {
                    int pl = (e + 1) / 49; float x = v.y;
                    if (pl == 0) a0 += x; else if (pl == 1) a1 += x;
                    else if (pl == 2) a2 += x; else a3 += x;
                }
                {
                    int pl = (e + 2) / 49; float x = v.z;
                    if (pl == 0) a0 += x; else if (pl == 1) a1 += x;
                    else if (pl == 2) a2 += x; else a3 += x;
                }
                {
                    int pl = (e + 3) / 49; float x = v.w;
                    if (pl == 0) a0 += x; else if (pl == 1) a1 += x;
                    else if (pl == 2) a2 += x; else a3 += x;
                }
            }
        }
        a0 = warp_reduce(a0);
        a1 = warp_reduce(a1);
        a2 = warp_reduce(a2);
        a3 = warp_reduce(a3);
        if (lane == 0) {
            const int plane0 = g * 4;
            const int b = plane0 >> 11, c = plane0 & 2047;  // C=2048
            float* dst = &g_v[b * CTOT + 1792 + c];
            dst[0] = a0 * (1.f / 49.f);
            dst[1] = a1 * (1.f / 49.f);
            dst[2] = a2 * (1.f / 49.f);
            dst[3] = a3 * (1.f / 49.f);
        }
    }
}

// ---------------------------------------------------------------------------
// GEMM with packed f32x2 FMA. Grid (8 e-tiles, 30 k-splits), 128 threads.
// Whole 128e x 128k W tile via cp.async (full MLP), v slice via LDG, one
// wait. Inner loop: microtile 8b x 4e, K packed in pairs -> fma.rn.f32x2
// (exact fp32; accumulator holds even/odd-k partial sums, summed at end).
// smem pitch 132 floats -> LDS.128 conflict-free.
// ---------------------------------------------------------------------------
#define GEMM_KSPLIT 30
#define GEMM_SMEM ((128 * 132 + 32 * 132) * 4)

__device__ __forceinline__ void ffma2(unsigned long long& d,
                                      unsigned long long a,
                                      unsigned long long b) {
    asm("fma.rn.f32x2 %0, %1, %2, %0;" : "+l"(d) : "l"(a), "l"(b));
}

__global__ __launch_bounds__(128)
void gemm_kernel(const float* __restrict__ w, float* __restrict__ out) {
    extern __shared__ float sm[];
    float* ws = sm;                 // [128][132]
    float* vs = sm + 128 * 132;     // [32][132]

    const int e0  = blockIdx.x * 128;
    const int k0  = blockIdx.y * 128;
    const int tid = threadIdx.x;

    // --- cp.async entire W tile: 128 rows x 32 f4-chunks = 4096 chunks ---
    #pragma unroll
    for (int r = 0; r < 32; r++) {
        const int cid = tid + r * 128;
        const int e   = cid >> 5;
        const int kc  = cid & 31;
        const float* src = w + (size_t)(e0 + e) * CTOT + k0 + kc * 4;
        unsigned dst = (unsigned)__cvta_generic_to_shared(&ws[e * 132 + kc * 4]);
        asm volatile("cp.async.cg.shared.global [%0], [%1], 16;\n"
                     :: "r"(dst), "l"(src));
    }
    asm volatile("cp.async.commit_group;\n");

    // --- v slice: 32 rows x 32 chunks, 8 f4 per thread ---
    #pragma unroll
    for (int r = 0; r < 8; r++) {
        const int i  = tid + r * 128;
        const int b  = i >> 5;
        const int kq = i & 31;
        float4 v4 = *(const float4*)&g_v[b * CTOT + k0 + kq * 4];
        *(float4*)&vs[b * 132 + kq * 4] = v4;
    }

    asm volatile("cp.async.wait_group 0;\n" ::: "memory");
    __syncthreads();

    // --- compute: microtile 8b x 4e, f32x2 along K ---
    const int lane = tid & 31;
    const int b0   = (tid >> 5) * 8;

    unsigned long long acc2[8][4];
    #pragma unroll
    for (int i = 0; i < 8; i++)
        #pragma unroll
        for (int j = 0; j < 4; j++) acc2[i][j] = 0ull;

    #pragma unroll 4
    for (int k4 = 0; k4 < 32; k4++) {
        float4 wv[4];
        #pragma unroll
        for (int j = 0; j < 4; j++)
            wv[j] = *(const float4*)&ws[(lane + 32 * j) * 132 + k4 * 4];
        #pragma unroll
        for (int i = 0; i < 8; i++) {
            float4 av = *(const float4*)&vs[(b0 + i) * 132 + k4 * 4];
            const unsigned long long* ap = (const unsigned long long*)&av;
            #pragma unroll
            for (int j = 0; j < 4; j++) {
                const unsigned long long* wp = (const unsigned long long*)&wv[j];
                ffma2(acc2[i][j], ap[0], wp[0]);   // k even/odd pair 0
                ffma2(acc2[i][j], ap[1], wp[1]);   // k even/odd pair 1
            }
        }
    }

    #pragma unroll
    for (int i = 0; i < 8; i++) {
        const int b = b0 + i;
        #pragma unroll
        for (int j = 0; j < 4; j++) {
            float2 r = *(const float2*)&acc2[i][j];
            atomicAdd(&out[b * EMB + e0 + lane + 32 * j], r.x + r.y);
        }
    }
}

// ---------------------------------------------------------------------------
extern "C" void kernel_launch(void* const* d_in, const int* in_sizes, int n_in,
                              void* d_out, int out_size) {
    const float* feat0  = (const float*)d_in[0];
    const float* feat1  = (const float*)d_in[1];
    const float* feat2  = (const float*)d_in[2];
    const float* feat3  = (const float*)d_in[3];
    const float* conv_w = (const float*)d_in[4];
    float* out = (float*)d_out;

    cudaFuncSetAttribute(gemm_kernel,
                         cudaFuncAttributeMaxDynamicSharedMemorySize, GEMM_SMEM);

    cudaMemsetAsync(d_out, 0, (size_t)out_size * sizeof(float), 0);

    fused_pool_kernel<<<NBLK_TOTAL, 256>>>(feat0, feat1, feat2, feat3);

    dim3 grid(EMB / 128, GEMM_KSPLIT);
    gemm_kernel<<<grid, 128, GEMM_SMEM>>>(conv_w, out);
}

// round 9
// speedup vs baseline: 3.4330x; 1.0201x over previous
#include <cuda_runtime.h>
#include <cuda_bf16.h>
#include <cstdint>

// ---------------------------------------------------------------------------
// out[32,1024] = concat_c( spatial_mean(feat_l) ) @ conv_w.T
// (bilinear half-pixel upsample at ratios 1,2,4,8 + mean == plain mean.)
// feat0 [32,256,56,56], feat1 [32,512,28,28], feat2 [32,1024,14,14],
// feat3 [32,2048,7,7], conv_w [1024,3840].
//
// Pool: fused warp-per-plane kernel at HBM roofline.
// GEMM: occupancy-first: tile 128e x 64k, 480 blocks (one full wave,
// ~3.2 blocks/SM), f32x2 FMA inner loop, split-K atomics.
// ---------------------------------------------------------------------------

#define BATCH 32
#define CTOT  3840
#define EMB   1024

__device__ float g_v[BATCH * CTOT];   // pooled vector [32,3840]

__device__ __forceinline__ float warp_reduce(float s) {
    #pragma unroll
    for (int o = 16; o > 0; o >>= 1)
        s += __shfl_down_sync(0xFFFFFFFFu, s, o);
    return s;
}

// ---------------------------------------------------------------------------
// Fused pooling kernel (unchanged — at HBM roofline).
// ---------------------------------------------------------------------------
#define NBLK0 1024
#define NBLK1 1024
#define NBLK2 2048
#define NBLK3 2048
#define NBLK_TOTAL (NBLK0 + NBLK1 + NBLK2 + NBLK3)

__global__ __launch_bounds__(256)
void fused_pool_kernel(const float* __restrict__ f0,
                       const float* __restrict__ f1,
                       const float* __restrict__ f2,
                       const float* __restrict__ f3) {
    const int blk  = blockIdx.x;
    const int lane = threadIdx.x & 31;
    const int warp = threadIdx.x >> 5;

    if (blk < NBLK0) {
        // ---- level 0: 56x56 = 784 f4, 1 plane per warp ----
        const int plane = blk * 8 + warp;
        const float4* __restrict__ p = (const float4*)f0 + (size_t)plane * 784;
        float a0 = 0.f, a1 = 0.f, a2 = 0.f, a3 = 0.f;
        #pragma unroll
        for (int k = 0; k < 6; k++) {
            float4 v0 = p[lane + (4 * k + 0) * 32];
            float4 v1 = p[lane + (4 * k + 1) * 32];
            float4 v2 = p[lane + (4 * k + 2) * 32];
            float4 v3 = p[lane + (4 * k + 3) * 32];
            a0 += (v0.x + v0.y) + (v0.z + v0.w);
            a1 += (v1.x + v1.y) + (v1.z + v1.w);
            a2 += (v2.x + v2.y) + (v2.z + v2.w);
            a3 += (v3.x + v3.y) + (v3.z + v3.w);
        }
        if (lane < 16) {
            float4 v = p[768 + lane];
            a0 += (v.x + v.y) + (v.z + v.w);
        }
        float s = warp_reduce((a0 + a1) + (a2 + a3));
        if (lane == 0) {
            const int b = plane >> 8, c = plane & 255;      // C=256
            g_v[b * CTOT + c] = s * (1.f / 3136.f);
        }
    } else if (blk < NBLK0 + NBLK1) {
        // ---- level 1: 28x28 = 196 f4, 2 planes per warp ----
        const int g = (blk - NBLK0) * 8 + warp;
        const int plane0 = g * 2;
        const float4* __restrict__ p = (const float4*)f1 + (size_t)plane0 * 196;
        float s0 = 0.f, s1 = 0.f;
        #pragma unroll
        for (int k = 0; k < 6; k++) {
            float4 v0 = p[lane + k * 32];
            float4 v1 = p[196 + lane + k * 32];
            s0 += (v0.x + v0.y) + (v0.z + v0.w);
            s1 += (v1.x + v1.y) + (v1.z + v1.w);
        }
        if (lane < 4) {
            float4 v0 = p[192 + lane];
            float4 v1 = p[196 + 192 + lane];
            s0 += (v0.x + v0.y) + (v0.z + v0.w);
            s1 += (v1.x + v1.y) + (v1.z + v1.w);
        }
        s0 = warp_reduce(s0);
        s1 = warp_reduce(s1);
        if (lane == 0) {
            const int b = plane0 >> 9, c = plane0 & 511;    // C=512
            g_v[b * CTOT + 256 + c]     = s0 * (1.f / 784.f);
            g_v[b * CTOT + 256 + c + 1] = s1 * (1.f / 784.f);
        }
    } else if (blk < NBLK0 + NBLK1 + NBLK2) {
        // ---- level 2: 14x14 = 49 f4, 2 planes per warp ----
        const int g = (blk - NBLK0 - NBLK1) * 8 + warp;
        const int plane0 = g * 2;
        const float4* __restrict__ p = (const float4*)f2 + (size_t)plane0 * 49;
        float s0, s1;
        {
            float4 v0 = p[lane];
            float4 v1 = p[49 + lane];
            s0 = (v0.x + v0.y) + (v0.z + v0.w);
            s1 = (v1.x + v1.y) + (v1.z + v1.w);
        }
        if (lane < 17) {
            float4 v0 = p[32 + lane];
            float4 v1 = p[49 + 32 + lane];
            s0 += (v0.x + v0.y) + (v0.z + v0.w);
            s1 += (v1.x + v1.y) + (v1.z + v1.w);
        }
        s0 = warp_reduce(s0);
        s1 = warp_reduce(s1);
        if (lane == 0) {
            const int b = plane0 >> 10, c = plane0 & 1023;  // C=1024
            g_v[b * CTOT + 768 + c]     = s0 * (1.f / 196.f);
            g_v[b * CTOT + 768 + c + 1] = s1 * (1.f / 196.f);
        }
    } else {
        // ---- level 3: 7x7 planes; warp handles 4 planes = 49 f4 ----
        const int g = (blk - NBLK0 - NBLK1 - NBLK2) * 8 + warp;
        const float4* __restrict__ p = (const float4*)f3 + (size_t)g * 49;

        float a0 = 0.f, a1 = 0.f, a2 = 0.f, a3 = 0.f;
        #pragma unroll
        for (int rep = 0; rep < 2; rep++) {
            const int i = lane + rep * 32;
            if (i < 49) {
                float4 v = p[i];
                const int e = 4 * i;
                {
                    int pl = e / 49; float x = v.x;
                    if (pl == 0) a0 += x; else if (pl == 1) a1 += x;
                    else if (pl == 2) a2 += x; else a3 += x;
                }
                {
                    int pl = (e + 1) / 49; float x = v.y;
                    if (pl == 0) a0 += x; else if (pl == 1) a1 += x;
                    else if (pl == 2) a2 += x; else a3 += x;
                }
                {
                    int pl = (e + 2) / 49; float x = v.z;
                    if (pl == 0) a0 += x; else if (pl == 1) a1 += x;
                    else if (pl == 2) a2 += x; else a3 += x;
                }
                {
                    int pl = (e + 3) / 49; float x = v.w;
                    if (pl == 0) a0 += x; else if (pl == 1) a1 += x;
                    else if (pl == 2) a2 += x; else a3 += x;
                }
            }
        }
        a0 = warp_reduce(a0);
        a1 = warp_reduce(a1);
        a2 = warp_reduce(a2);
        a3 = warp_reduce(a3);
        if (lane == 0) {
            const int plane0 = g * 4;
            const int b = plane0 >> 11, c = plane0 & 2047;  // C=2048
            float* dst = &g_v[b * CTOT + 1792 + c];
            dst[0] = a0 * (1.f / 49.f);
            dst[1] = a1 * (1.f / 49.f);
            dst[2] = a2 * (1.f / 49.f);
            dst[3] = a3 * (1.f / 49.f);
        }
    }
}

// ---------------------------------------------------------------------------
// GEMM: grid (8 e-tiles, 60 k-splits) = 480 blocks x 128 threads — one full
// resident wave (~3.2 blocks/SM, smem 43.5KB). Tile 128e x 64k. cp.async W,
// LDG v, one wait. Microtile 8b x 4e with fma.rn.f32x2 along K.
// smem pitch 68 floats (68 mod 32 = 4 -> conflict-free LDS.128 phases).
// ---------------------------------------------------------------------------
#define GEMM_KSPLIT 60
#define GEMM_KTILE  64
#define GEMM_NK4    16
#define GEMM_PITCH  68
#define GEMM_SMEM ((128 * GEMM_PITCH + 32 * GEMM_PITCH) * 4)

__device__ __forceinline__ void ffma2(unsigned long long& d,
                                      unsigned long long a,
                                      unsigned long long b) {
    asm("fma.rn.f32x2 %0, %1, %2, %0;" : "+l"(d) : "l"(a), "l"(b));
}

__global__ __launch_bounds__(128)
void gemm_kernel(const float* __restrict__ w, float* __restrict__ out) {
    extern __shared__ float sm[];
    float* ws = sm;                        // [128][68]
    float* vs = sm + 128 * GEMM_PITCH;     // [32][68]

    const int e0  = blockIdx.x * 128;
    const int k0  = blockIdx.y * GEMM_KTILE;
    const int tid = threadIdx.x;

    // --- cp.async W tile: 128 rows x 16 f4-chunks = 2048 chunks, 16/thread ---
    #pragma unroll
    for (int r = 0; r < 16; r++) {
        const int cid = tid + r * 128;
        const int e   = cid >> 4;
        const int kc  = cid & 15;
        const float* src = w + (size_t)(e0 + e) * CTOT + k0 + kc * 4;
        unsigned dst = (unsigned)__cvta_generic_to_shared(&ws[e * GEMM_PITCH + kc * 4]);
        asm volatile("cp.async.cg.shared.global [%0], [%1], 16;\n"
                     :: "r"(dst), "l"(src));
    }
    asm volatile("cp.async.commit_group;\n");

    // --- v slice: 32 rows x 16 chunks = 512 f4, 4 per thread ---
    #pragma unroll
    for (int r = 0; r < 4; r++) {
        const int i  = tid + r * 128;
        const int b  = i >> 4;
        const int kq = i & 15;
        float4 v4 = *(const float4*)&g_v[b * CTOT + k0 + kq * 4];
        *(float4*)&vs[b * GEMM_PITCH + kq * 4] = v4;
    }

    asm volatile("cp.async.wait_group 0;\n" ::: "memory");
    __syncthreads();

    // --- compute: microtile 8b x 4e, f32x2 along K ---
    const int lane = tid & 31;
    const int b0   = (tid >> 5) * 8;

    unsigned long long acc2[8][4];
    #pragma unroll
    for (int i = 0; i < 8; i++)
        #pragma unroll
        for (int j = 0; j < 4; j++) acc2[i][j] = 0ull;

    #pragma unroll 4
    for (int k4 = 0; k4 < GEMM_NK4; k4++) {
        float4 wv[4];
        #pragma unroll
        for (int j = 0; j < 4; j++)
            wv[j] = *(const float4*)&ws[(lane + 32 * j) * GEMM_PITCH + k4 * 4];
        #pragma unroll
        for (int i = 0; i < 8; i++) {
            float4 av = *(const float4*)&vs[(b0 + i) * GEMM_PITCH + k4 * 4];
            const unsigned long long* ap = (const unsigned long long*)&av;
            #pragma unroll
            for (int j = 0; j < 4; j++) {
                const unsigned long long* wp = (const unsigned long long*)&wv[j];
                ffma2(acc2[i][j], ap[0], wp[0]);
                ffma2(acc2[i][j], ap[1], wp[1]);
            }
        }
    }

    #pragma unroll
    for (int i = 0; i < 8; i++) {
        const int b = b0 + i;
        #pragma unroll
        for (int j = 0; j < 4; j++) {
            float2 r = *(const float2*)&acc2[i][j];
            atomicAdd(&out[b * EMB + e0 + lane + 32 * j], r.x + r.y);
        }
    }
}

// ---------------------------------------------------------------------------
extern "C" void kernel_launch(void* const* d_in, const int* in_sizes, int n_in,
                              void* d_out, int out_size) {
    const float* feat0  = (const float*)d_in[0];
    const float* feat1  = (const float*)d_in[1];
    const float* feat2  = (const float*)d_in[2];
    const float* feat3  = (const float*)d_in[3];
    const float* conv_w = (const float*)d_in[4];
    float* out = (float*)d_out;

    cudaFuncSetAttribute(gemm_kernel,
                         cudaFuncAttributeMaxDynamicSharedMemorySize, GEMM_SMEM);

    cudaMemsetAsync(d_out, 0, (size_t)out_size * sizeof(float), 0);

    fused_pool_kernel<<<NBLK_TOTAL, 256>>>(feat0, feat1, feat2, feat3);

    dim3 grid(EMB / 128, GEMM_KSPLIT);
    gemm_kernel<<<grid, 128, GEMM_SMEM>>>(conv_w, out);
}